// round 1
// baseline (speedup 1.0000x reference)
#include <cuda_runtime.h>
#include <math.h>

#define B_   4
#define S_   2048
#define E_   1024
#define NH_  16
#define HD_  64
#define M_   (B_ * S_)        // 8192
#define QKV_ (3 * NH_ * HD_)  // 3072
#define NHD_ (NH_ * HD_)      // 1024

// Scratch (device globals — no allocations allowed)
__device__ float g_q[B_ * NH_ * S_ * HD_];   // [B,N,S,H]
__device__ float g_k[B_ * NH_ * S_ * HD_];
__device__ float g_v[B_ * NH_ * S_ * HD_];
__device__ float g_ao[B_ * S_ * NHD_];       // [B,S,N*H]

// ---------------------------------------------------------------------------
// Classic 128x128x8 SGEMM, 256 threads, 8x8 per-thread register tile.
// MODE 0: C[m,col] = g_ao @ Bm + bias   (out projection, A read from g_ao)
// MODE 1: qkv = Ain @ Bm + bias, scattered into g_q/g_k/g_v [B,N,S,H]
// ---------------------------------------------------------------------------
template <int MODE>
__global__ __launch_bounds__(256)
void sgemm_kernel(const float* __restrict__ Ain, const float* __restrict__ Bm,
                  const float* __restrict__ bias, float* __restrict__ C,
                  int M, int Nn, int K)
{
    const float* A = (MODE == 0) ? g_ao : Ain;
    __shared__ float As[8][128];
    __shared__ float Bs[8][128];

    const int tid  = threadIdx.x;
    const int bm   = blockIdx.y * 128;
    const int bn   = blockIdx.x * 128;
    const int arow = tid >> 1;
    const int aseg = (tid & 1) * 4;
    const int brow = tid >> 5;
    const int bcol = (tid & 31) * 4;
    const float* Ap = A + (size_t)(bm + arow) * K + aseg;
    const float* Bp = Bm + (size_t)brow * Nn + bn + bcol;

    float acc[8][8];
#pragma unroll
    for (int i = 0; i < 8; i++)
#pragma unroll
        for (int j = 0; j < 8; j++) acc[i][j] = 0.f;

    const int tx = tid & 15;
    const int ty = tid >> 4;

    for (int k0 = 0; k0 < K; k0 += 8) {
        float4 av = *(const float4*)(Ap + k0);
        float4 bv = *(const float4*)(Bp + (size_t)k0 * Nn);
        As[aseg + 0][arow] = av.x;
        As[aseg + 1][arow] = av.y;
        As[aseg + 2][arow] = av.z;
        As[aseg + 3][arow] = av.w;
        *(float4*)&Bs[brow][bcol] = bv;
        __syncthreads();
#pragma unroll
        for (int kk = 0; kk < 8; kk++) {
            float4 a0 = *(const float4*)&As[kk][ty * 8];
            float4 a1 = *(const float4*)&As[kk][ty * 8 + 4];
            float4 b0 = *(const float4*)&Bs[kk][tx * 8];
            float4 b1 = *(const float4*)&Bs[kk][tx * 8 + 4];
            float ar[8] = {a0.x, a0.y, a0.z, a0.w, a1.x, a1.y, a1.z, a1.w};
            float br[8] = {b0.x, b0.y, b0.z, b0.w, b1.x, b1.y, b1.z, b1.w};
#pragma unroll
            for (int i = 0; i < 8; i++)
#pragma unroll
                for (int j = 0; j < 8; j++)
                    acc[i][j] = fmaf(ar[i], br[j], acc[i][j]);
        }
        __syncthreads();
    }

#pragma unroll
    for (int i = 0; i < 8; i++) {
        const int m = bm + ty * 8 + i;
        const int b = m >> 11;          // /S_
        const int s = m & (S_ - 1);
#pragma unroll
        for (int j = 0; j < 8; j++) {
            const int col = bn + tx * 8 + j;
            const float v = acc[i][j] + bias[col];
            if (MODE == 0) {
                C[(size_t)m * Nn + col] = v;
            } else {
                const int which = col >> 10;   // 0=q,1=k,2=v
                const int rem   = col & 1023;
                const int n     = rem >> 6;
                const int h     = rem & 63;
                float* dst = (which == 0) ? g_q : (which == 1) ? g_k : g_v;
                dst[(((size_t)b * NH_ + n) * S_ + s) * HD_ + h] = v;
            }
        }
    }
}

// ---------------------------------------------------------------------------
// fp32 flash attention, causal. 64 queries x 64 keys per tile, 256 threads.
// Thread (ty,tx) (16x16) owns q rows {ty+16i}, k/h cols {tx+16j}, 4x4 frags.
// ---------------------------------------------------------------------------
#define PIT 65  // smem pitch (bank-conflict padding)

__global__ __launch_bounds__(256)
void flash_kernel()
{
    extern __shared__ float sm[];
    float* Qs = sm;                 // [64][PIT]
    float* Ks = Qs + 64 * PIT;
    float* Vs = Ks + 64 * PIT;
    float* Ps = Vs + 64 * PIT;

    const int tid = threadIdx.x;
    const int qt  = blockIdx.x;     // query tile
    const int bn  = blockIdx.y;     // b*NH + n
    const float* Qb = g_q + ((size_t)bn * S_ + (size_t)qt * 64) * HD_;
    const float* Kb = g_k + (size_t)bn * S_ * HD_;
    const float* Vb = g_v + (size_t)bn * S_ * HD_;

#pragma unroll
    for (int i = 0; i < 16; i++) {
        int idx = tid + i * 256;
        Qs[(idx >> 6) * PIT + (idx & 63)] = Qb[idx];
    }

    const int tx = tid & 15;
    const int ty = tid >> 4;

    float Oacc[4][4];
#pragma unroll
    for (int i = 0; i < 4; i++)
#pragma unroll
        for (int j = 0; j < 4; j++) Oacc[i][j] = 0.f;
    float mrow[4] = {-1e30f, -1e30f, -1e30f, -1e30f};
    float lrow[4] = {0.f, 0.f, 0.f, 0.f};

    for (int kt = 0; kt <= qt; kt++) {
        const float* Kp = Kb + (size_t)kt * 64 * HD_;
        const float* Vp = Vb + (size_t)kt * 64 * HD_;
#pragma unroll
        for (int i = 0; i < 16; i++) {
            int idx = tid + i * 256;
            int r = idx >> 6, c = idx & 63;
            Ks[r * PIT + c] = Kp[idx];
            Vs[r * PIT + c] = Vp[idx];
        }
        __syncthreads();

        // S = Q K^T (scaled)
        float s[4][4];
#pragma unroll
        for (int i = 0; i < 4; i++)
#pragma unroll
            for (int j = 0; j < 4; j++) s[i][j] = 0.f;
#pragma unroll
        for (int d = 0; d < 64; d++) {
            float qv[4], kv[4];
#pragma unroll
            for (int i = 0; i < 4; i++) qv[i] = Qs[(ty + 16 * i) * PIT + d];
#pragma unroll
            for (int j = 0; j < 4; j++) kv[j] = Ks[(tx + 16 * j) * PIT + d];
#pragma unroll
            for (int i = 0; i < 4; i++)
#pragma unroll
                for (int j = 0; j < 4; j++)
                    s[i][j] = fmaf(qv[i], kv[j], s[i][j]);
        }

        const bool diag = (kt == qt);
#pragma unroll
        for (int i = 0; i < 4; i++)
#pragma unroll
            for (int j = 0; j < 4; j++) {
                s[i][j] *= 0.125f;  // 1/sqrt(64)
                if (diag && (tx + 16 * j) > (ty + 16 * i)) s[i][j] = -1e30f;
            }

        // online softmax + P stash
#pragma unroll
        for (int i = 0; i < 4; i++) {
            float tm = fmaxf(fmaxf(s[i][0], s[i][1]), fmaxf(s[i][2], s[i][3]));
#pragma unroll
            for (int off = 8; off > 0; off >>= 1)
                tm = fmaxf(tm, __shfl_xor_sync(0xffffffffu, tm, off, 16));
            const float mn   = fmaxf(mrow[i], tm);
            const float corr = __expf(mrow[i] - mn);
            mrow[i] = mn;
            float rs = 0.f;
#pragma unroll
            for (int j = 0; j < 4; j++) {
                s[i][j] = __expf(s[i][j] - mn);
                rs += s[i][j];
            }
#pragma unroll
            for (int off = 8; off > 0; off >>= 1)
                rs += __shfl_xor_sync(0xffffffffu, rs, off, 16);
            lrow[i] = lrow[i] * corr + rs;
#pragma unroll
            for (int j = 0; j < 4; j++) {
                Oacc[i][j] *= corr;
                Ps[(ty + 16 * i) * PIT + tx + 16 * j] = s[i][j];
            }
        }
        __syncthreads();

        // O += P V
#pragma unroll 8
        for (int k = 0; k < 64; k++) {
            float pv[4], vv[4];
#pragma unroll
            for (int i = 0; i < 4; i++) pv[i] = Ps[(ty + 16 * i) * PIT + k];
#pragma unroll
            for (int j = 0; j < 4; j++) vv[j] = Vs[k * PIT + tx + 16 * j];
#pragma unroll
            for (int i = 0; i < 4; i++)
#pragma unroll
                for (int j = 0; j < 4; j++)
                    Oacc[i][j] = fmaf(pv[i], vv[j], Oacc[i][j]);
        }
        __syncthreads();
    }

    const int b = bn >> 4;
    const int n = bn & 15;
#pragma unroll
    for (int i = 0; i < 4; i++) {
        const int sg = qt * 64 + ty + 16 * i;
        const float inv = 1.f / lrow[i];
#pragma unroll
        for (int j = 0; j < 4; j++)
            g_ao[((size_t)b * S_ + sg) * NHD_ + n * 64 + tx + 16 * j] =
                Oacc[i][j] * inv;
    }
}

// ---------------------------------------------------------------------------
extern "C" void kernel_launch(void* const* d_in, const int* in_sizes, int n_in,
                              void* d_out, int out_size)
{
    const float* x    = (const float*)d_in[0];
    const float* Wqkv = (const float*)d_in[1];
    const float* bqkv = (const float*)d_in[2];
    const float* Wout = (const float*)d_in[3];
    const float* bout = (const float*)d_in[4];
    float* out = (float*)d_out;

    const size_t flash_smem = 4 * 64 * PIT * sizeof(float);  // 66560 B
    cudaFuncSetAttribute(flash_kernel,
                         cudaFuncAttributeMaxDynamicSharedMemorySize,
                         (int)flash_smem);

    dim3 blk(256);
    // 1) fused QKV projection + bias + head-transpose scatter
    sgemm_kernel<1><<<dim3(QKV_ / 128, M_ / 128), blk>>>(
        x, Wqkv, bqkv, nullptr, M_, QKV_, E_);
    // 2) causal flash attention -> g_ao [B,S,N*H]
    flash_kernel<<<dim3(S_ / 64, B_ * NH_), blk, flash_smem>>>();
    // 3) output projection + bias -> d_out
    sgemm_kernel<0><<<dim3(E_ / 128, M_ / 128), blk>>>(
        nullptr, Wout, bout, out, M_, E_, NHD_);
}

// round 6
// speedup vs baseline: 1.7853x; 1.7853x over previous
#include <cuda_runtime.h>
#include <cstdint>
#include <math.h>

#define B_   4
#define S_   2048
#define E_   1024
#define NH_  16
#define HD_  64
#define M_   (B_ * S_)        // 8192
#define QKV_ (3 * NH_ * HD_)  // 3072
#define NHD_ (NH_ * HD_)      // 1024
#define KD   1024             // K dim of both projection GEMMs
#define NCH  (KD / 32)        // 32 k-chunks of 32 elements
#define APITCH 36             // As pitch (floats): conflict-free fragment loads
#define BPITCH 132            // Bs pitch (floats)

// ---- scratch: EXACTLY 128 MiB total (the R1-proven footprint) --------------
__device__ float g_q[B_ * NH_ * S_ * HD_];   // [B,N,S,H]  32 MiB
__device__ float g_k[B_ * NH_ * S_ * HD_];   //            32 MiB
__device__ float g_v[B_ * NH_ * S_ * HD_];   //            32 MiB
__device__ float g_ao[B_ * S_ * NHD_];       // [B,S,N*H]  32 MiB (tf32-rounded)

// ---------------- helpers ---------------------------------------------------
__device__ __forceinline__ float tf32_rna(float f) {
    uint32_t u;
    asm("cvt.rna.tf32.f32 %0, %1;" : "=r"(u) : "f"(f));
    return __uint_as_float(u);
}
// MMA macro: accumulator lvalues bind directly; no arrays through pointers.
#define MMA_TF32(c0, c1, c2, c3, a0, a1, a2, a3, b0, b1)                      \
    asm volatile(                                                             \
        "mma.sync.aligned.m16n8k8.row.col.f32.tf32.tf32.f32 "                 \
        "{%0,%1,%2,%3}, {%4,%5,%6,%7}, {%8,%9}, {%0,%1,%2,%3};"               \
        : "+f"(c0), "+f"(c1), "+f"(c2), "+f"(c3)                              \
        : "r"(a0), "r"(a1), "r"(a2), "r"(a3), "r"(b0), "r"(b1))

// ---------------------------------------------------------------------------
// TF32 mma.sync GEMM, C[128x128 tile] = A[M,1024] @ W[1024,Nn] + bias
// A rounded to tf32 on the fly; W read in natural [K][N] layout (no transpose).
// MODE 1: A=x, W=W_qkv (Nn=3072) -> scatter into g_q/g_k/g_v [B,N,S,H]
// MODE 0: A=g_ao, W=W_out (Nn=1024) -> Cout row-major
// 256 threads = 8 warps (2m x 4n), warp tile 64x32, m16n8k8 frags.
// smem: As[2][128][36] (36864B) + Bs[2][32][132] (33792B) = 70656 B
template <int MODE>
__global__ __launch_bounds__(256)
void mma_gemm(const float* __restrict__ Ain, const float* __restrict__ W,
              const float* __restrict__ bias, float* __restrict__ Cout)
{
    const int NW = (MODE == 1) ? QKV_ : NHD_;
    extern __shared__ float smf[];
    float* As = smf;                     // 2 x [128][APITCH]
    float* Bs = smf + 2 * 128 * APITCH;  // 2 x [32][BPITCH]

    const int tid  = threadIdx.x;
    const int wid  = tid >> 5;
    const int lane = tid & 31;
    const int warpM = wid & 1;
    const int warpN = wid >> 1;
    const int t4  = lane >> 2;
    const int tm4 = lane & 3;

    const int bn = blockIdx.x * 128, bm = blockIdx.y * 128;
    const float* A = (MODE == 0) ? g_ao : Ain;

    // loader geometry
    const int am  = tid >> 3;            // A row 0..31 (+32 per q)
    const int ak4 = (tid & 7) * 4;       // A k offset
    const int bk  = tid >> 5;            // B row 0..7 (+8 per q)
    const int bn4 = (tid & 31) * 4;      // B n offset
    const float* Aptr = A + (size_t)(bm + am) * KD + ak4;
    const float* Wptr = W + (size_t)bk * NW + bn + bn4;

    float4 pa[4], pb[4];
#pragma unroll
    for (int q = 0; q < 4; q++) {
        pa[q] = *(const float4*)(Aptr + (size_t)(q * 32) * KD);
        pb[q] = *(const float4*)(Wptr + (size_t)(q * 8) * NW);
    }

    float acc[4][4][4];
#pragma unroll
    for (int mf = 0; mf < 4; mf++)
#pragma unroll
        for (int nf = 0; nf < 4; nf++)
#pragma unroll
            for (int e = 0; e < 4; e++) acc[mf][nf][e] = 0.f;

    // store prologue chunk to stage 0 (with tf32 rounding)
#pragma unroll
    for (int q = 0; q < 4; q++) {
        float* d = As + (am + q * 32) * APITCH + ak4;
        d[0] = tf32_rna(pa[q].x); d[1] = tf32_rna(pa[q].y);
        d[2] = tf32_rna(pa[q].z); d[3] = tf32_rna(pa[q].w);
        float* e = Bs + (bk + q * 8) * BPITCH + bn4;
        e[0] = tf32_rna(pb[q].x); e[1] = tf32_rna(pb[q].y);
        e[2] = tf32_rna(pb[q].z); e[3] = tf32_rna(pb[q].w);
    }
    __syncthreads();

    for (int ch = 0; ch < NCH; ch++) {
        // prefetch next chunk into registers (overlaps with compute)
        if (ch + 1 < NCH) {
            const int k0 = (ch + 1) * 32;
#pragma unroll
            for (int q = 0; q < 4; q++) {
                pa[q] = *(const float4*)(Aptr + (size_t)(q * 32) * KD + k0);
                pb[q] = *(const float4*)(Wptr + (size_t)(k0 + q * 8) * NW);
            }
        }

        const float* Sa = As + (ch & 1) * 128 * APITCH;
        const float* Sb = Bs + (ch & 1) * 32 * BPITCH;
#pragma unroll
        for (int ks = 0; ks < 4; ks++) {
            const int kk = ks * 8;
            uint32_t a[4][4], b[4][2];
#pragma unroll
            for (int mf = 0; mf < 4; mf++) {
                const float* pav = Sa + (warpM * 64 + mf * 16 + t4) * APITCH + kk + tm4;
                a[mf][0] = __float_as_uint(pav[0]);
                a[mf][1] = __float_as_uint(pav[8 * APITCH]);
                a[mf][2] = __float_as_uint(pav[4]);
                a[mf][3] = __float_as_uint(pav[8 * APITCH + 4]);
            }
#pragma unroll
            for (int nf = 0; nf < 4; nf++) {
                const float* pbv = Sb + (kk + tm4) * BPITCH + warpN * 32 + nf * 8 + t4;
                b[nf][0] = __float_as_uint(pbv[0]);
                b[nf][1] = __float_as_uint(pbv[4 * BPITCH]);
            }
#pragma unroll
            for (int mf = 0; mf < 4; mf++)
#pragma unroll
                for (int nf = 0; nf < 4; nf++)
                    MMA_TF32(acc[mf][nf][0], acc[mf][nf][1], acc[mf][nf][2], acc[mf][nf][3],
                             a[mf][0], a[mf][1], a[mf][2], a[mf][3],
                             b[nf][0], b[nf][1]);
        }

        if (ch + 1 < NCH) {
            float* Da = As + ((ch + 1) & 1) * 128 * APITCH;
            float* Db = Bs + ((ch + 1) & 1) * 32 * BPITCH;
#pragma unroll
            for (int q = 0; q < 4; q++) {
                float* d = Da + (am + q * 32) * APITCH + ak4;
                d[0] = tf32_rna(pa[q].x); d[1] = tf32_rna(pa[q].y);
                d[2] = tf32_rna(pa[q].z); d[3] = tf32_rna(pa[q].w);
                float* e = Db + (bk + q * 8) * BPITCH + bn4;
                e[0] = tf32_rna(pb[q].x); e[1] = tf32_rna(pb[q].y);
                e[2] = tf32_rna(pb[q].z); e[3] = tf32_rna(pb[q].w);
            }
        }
        __syncthreads();
    }

    // epilogue: c0,c1 -> (row, col, col+1); c2,c3 -> (row+8, ...)
#pragma unroll
    for (int mf = 0; mf < 4; mf++) {
#pragma unroll
        for (int nf = 0; nf < 4; nf++) {
            const int col = bn + warpN * 32 + nf * 8 + 2 * tm4;
            const float2 bv = *(const float2*)(bias + col);
#pragma unroll
            for (int half = 0; half < 2; half++) {
                const int m = bm + warpM * 64 + mf * 16 + t4 + half * 8;
                float2 o;
                o.x = acc[mf][nf][half * 2 + 0] + bv.x;
                o.y = acc[mf][nf][half * 2 + 1] + bv.y;
                if (MODE == 0) {
                    *(float2*)(Cout + (size_t)m * NHD_ + col) = o;
                } else {
                    const int b = m >> 11;
                    const int s = m & (S_ - 1);
                    const int which = col >> 10;
                    const int rem   = col & 1023;
                    const int n = rem >> 6;
                    const int h = rem & 63;
                    float* dst = (which == 0) ? g_q : (which == 1) ? g_k : g_v;
                    *(float2*)(dst + (((size_t)b * NH_ + n) * S_ + s) * HD_ + h) = o;
                }
            }
        }
    }
}

// ---------------------------------------------------------------------------
// fp32 flash attention, causal. 64x64 tiles, 256 threads (R1-proven; epilogue
// rounds to tf32 so the out-projection A operand is pre-rounded).
#define PIT 65

__global__ __launch_bounds__(256)
void flash_kernel()
{
    extern __shared__ float sm[];
    float* Qs = sm;
    float* Ks = Qs + 64 * PIT;
    float* Vs = Ks + 64 * PIT;
    float* Ps = Vs + 64 * PIT;

    const int tid = threadIdx.x;
    const int qt  = blockIdx.x;
    const int bn  = blockIdx.y;
    const float* Qb = g_q + ((size_t)bn * S_ + (size_t)qt * 64) * HD_;
    const float* Kb = g_k + (size_t)bn * S_ * HD_;
    const float* Vb = g_v + (size_t)bn * S_ * HD_;

#pragma unroll
    for (int i = 0; i < 16; i++) {
        int idx = tid + i * 256;
        Qs[(idx >> 6) * PIT + (idx & 63)] = Qb[idx];
    }
    const int tx = tid & 15;
    const int ty = tid >> 4;

    float Oacc[4][4];
#pragma unroll
    for (int i = 0; i < 4; i++)
#pragma unroll
        for (int j = 0; j < 4; j++) Oacc[i][j] = 0.f;
    float mrow[4] = {-1e30f, -1e30f, -1e30f, -1e30f};
    float lrow[4] = {0.f, 0.f, 0.f, 0.f};

    for (int kt = 0; kt <= qt; kt++) {
        const float* Kp = Kb + (size_t)kt * 64 * HD_;
        const float* Vp = Vb + (size_t)kt * 64 * HD_;
#pragma unroll
        for (int i = 0; i < 16; i++) {
            int idx = tid + i * 256;
            int r = idx >> 6, c = idx & 63;
            Ks[r * PIT + c] = Kp[idx];
            Vs[r * PIT + c] = Vp[idx];
        }
        __syncthreads();

        float s[4][4];
#pragma unroll
        for (int i = 0; i < 4; i++)
#pragma unroll
            for (int j = 0; j < 4; j++) s[i][j] = 0.f;
#pragma unroll
        for (int d = 0; d < 64; d++) {
            float qv[4], kv[4];
#pragma unroll
            for (int i = 0; i < 4; i++) qv[i] = Qs[(ty + 16 * i) * PIT + d];
#pragma unroll
            for (int j = 0; j < 4; j++) kv[j] = Ks[(tx + 16 * j) * PIT + d];
#pragma unroll
            for (int i = 0; i < 4; i++)
#pragma unroll
                for (int j = 0; j < 4; j++)
                    s[i][j] = fmaf(qv[i], kv[j], s[i][j]);
        }

        const bool diag = (kt == qt);
#pragma unroll
        for (int i = 0; i < 4; i++)
#pragma unroll
            for (int j = 0; j < 4; j++) {
                s[i][j] *= 0.125f;
                if (diag && (tx + 16 * j) > (ty + 16 * i)) s[i][j] = -1e30f;
            }

#pragma unroll
        for (int i = 0; i < 4; i++) {
            float tm = fmaxf(fmaxf(s[i][0], s[i][1]), fmaxf(s[i][2], s[i][3]));
#pragma unroll
            for (int off = 8; off > 0; off >>= 1)
                tm = fmaxf(tm, __shfl_xor_sync(0xffffffffu, tm, off, 16));
            const float mn   = fmaxf(mrow[i], tm);
            const float corr = __expf(mrow[i] - mn);
            mrow[i] = mn;
            float rs = 0.f;
#pragma unroll
            for (int j = 0; j < 4; j++) {
                s[i][j] = __expf(s[i][j] - mn);
                rs += s[i][j];
            }
#pragma unroll
            for (int off = 8; off > 0; off >>= 1)
                rs += __shfl_xor_sync(0xffffffffu, rs, off, 16);
            lrow[i] = lrow[i] * corr + rs;
#pragma unroll
            for (int j = 0; j < 4; j++) {
                Oacc[i][j] *= corr;
                Ps[(ty + 16 * i) * PIT + tx + 16 * j] = s[i][j];
            }
        }
        __syncthreads();

#pragma unroll 8
        for (int k = 0; k < 64; k++) {
            float pv[4], vv[4];
#pragma unroll
            for (int i = 0; i < 4; i++) pv[i] = Ps[(ty + 16 * i) * PIT + k];
#pragma unroll
            for (int j = 0; j < 4; j++) vv[j] = Vs[k * PIT + tx + 16 * j];
#pragma unroll
            for (int i = 0; i < 4; i++)
#pragma unroll
                for (int j = 0; j < 4; j++)
                    Oacc[i][j] = fmaf(pv[i], vv[j], Oacc[i][j]);
        }
        __syncthreads();
    }

    const int b = bn >> 4;
    const int n = bn & 15;
#pragma unroll
    for (int i = 0; i < 4; i++) {
        const int sg = qt * 64 + ty + 16 * i;
        const float inv = 1.f / lrow[i];
#pragma unroll
        for (int j = 0; j < 4; j++)
            g_ao[((size_t)b * S_ + sg) * NHD_ + n * 64 + tx + 16 * j] =
                tf32_rna(Oacc[i][j] * inv);
    }
}

// ---------------------------------------------------------------------------
extern "C" void kernel_launch(void* const* d_in, const int* in_sizes, int n_in,
                              void* d_out, int out_size)
{
    const float* x    = (const float*)d_in[0];
    const float* Wqkv = (const float*)d_in[1];
    const float* bqkv = (const float*)d_in[2];
    const float* Wout = (const float*)d_in[3];
    const float* bout = (const float*)d_in[4];
    float* out = (float*)d_out;

    const int gemm_smem  = (2 * 128 * APITCH + 2 * 32 * BPITCH) * sizeof(float); // 70656
    const int flash_smem = 4 * 64 * PIT * sizeof(float);                          // 66560
    cudaFuncSetAttribute(mma_gemm<1>, cudaFuncAttributeMaxDynamicSharedMemorySize, gemm_smem);
    cudaFuncSetAttribute(mma_gemm<0>, cudaFuncAttributeMaxDynamicSharedMemorySize, gemm_smem);
    cudaFuncSetAttribute(flash_kernel, cudaFuncAttributeMaxDynamicSharedMemorySize, flash_smem);

    // 1) QKV projection (mma.sync tf32, on-the-fly rounding) + bias + scatter
    mma_gemm<1><<<dim3(QKV_ / 128, M_ / 128), 256, gemm_smem>>>(x, Wqkv, bqkv, nullptr);
    // 2) causal flash attention -> g_ao
    flash_kernel<<<dim3(S_ / 64, B_ * NH_), 256, flash_smem>>>();
    // 3) output projection + bias -> d_out
    mma_gemm<0><<<dim3(NHD_ / 128, M_ / 128), 256, gemm_smem>>>(nullptr, Wout, bout, out);
}

// round 7
// speedup vs baseline: 3.4421x; 1.9281x over previous
#include <cuda_runtime.h>
#include <cstdint>
#include <math.h>

#define B_   4
#define S_   2048
#define E_   1024
#define NH_  16
#define HD_  64
#define M_   (B_ * S_)        // 8192
#define QKV_ (3 * NH_ * HD_)  // 3072
#define NHD_ (NH_ * HD_)      // 1024
#define KD   1024
#define NCH  (KD / 32)
#define APITCH 36
#define BPITCH 132

// ---- scratch: EXACTLY 128 MiB total (proven safe footprint) ----------------
__device__ float g_q[B_ * NH_ * S_ * HD_];   // [B,N,S,H]
__device__ float g_k[B_ * NH_ * S_ * HD_];   // [B,N,H,S]  (d-major for flash!)
__device__ float g_v[B_ * NH_ * S_ * HD_];   // [B,N,S,H]
__device__ float g_ao[B_ * S_ * NHD_];       // [B,S,N*H]

// ---------------- helpers ---------------------------------------------------
__device__ __forceinline__ float tf32_rna(float f) {
    uint32_t u;
    asm("cvt.rna.tf32.f32 %0, %1;" : "=r"(u) : "f"(f));
    return __uint_as_float(u);
}
#define MMA_TF32(c0, c1, c2, c3, a0, a1, a2, a3, b0, b1)                      \
    asm volatile(                                                             \
        "mma.sync.aligned.m16n8k8.row.col.f32.tf32.tf32.f32 "                 \
        "{%0,%1,%2,%3}, {%4,%5,%6,%7}, {%8,%9}, {%0,%1,%2,%3};"               \
        : "+f"(c0), "+f"(c1), "+f"(c2), "+f"(c3)                              \
        : "r"(a0), "r"(a1), "r"(a2), "r"(a3), "r"(b0), "r"(b1))

// ---------------------------------------------------------------------------
// TF32 mma.sync GEMM (unchanged engine from R6).
// MODE 1: x @ W_qkv + b -> q/k/v. Q,V stored [B,N,S,H]; K stored [B,N,H,S].
//         All q/k/v values tf32-rounded at store (flash MMA inputs).
// MODE 0: g_ao @ W_out + b -> Cout row-major.
template <int MODE>
__global__ __launch_bounds__(256)
void mma_gemm(const float* __restrict__ Ain, const float* __restrict__ W,
              const float* __restrict__ bias, float* __restrict__ Cout)
{
    const int NW = (MODE == 1) ? QKV_ : NHD_;
    extern __shared__ float smf[];
    float* As = smf;
    float* Bs = smf + 2 * 128 * APITCH;

    const int tid  = threadIdx.x;
    const int wid  = tid >> 5;
    const int lane = tid & 31;
    const int warpM = wid & 1;
    const int warpN = wid >> 1;
    const int t4  = lane >> 2;
    const int tm4 = lane & 3;

    const int bn = blockIdx.x * 128, bm = blockIdx.y * 128;
    const float* A = (MODE == 0) ? g_ao : Ain;

    const int am  = tid >> 3;
    const int ak4 = (tid & 7) * 4;
    const int bk  = tid >> 5;
    const int bn4 = (tid & 31) * 4;
    const float* Aptr = A + (size_t)(bm + am) * KD + ak4;
    const float* Wptr = W + (size_t)bk * NW + bn + bn4;

    float4 pa[4], pb[4];
#pragma unroll
    for (int q = 0; q < 4; q++) {
        pa[q] = *(const float4*)(Aptr + (size_t)(q * 32) * KD);
        pb[q] = *(const float4*)(Wptr + (size_t)(q * 8) * NW);
    }

    float acc[4][4][4];
#pragma unroll
    for (int mf = 0; mf < 4; mf++)
#pragma unroll
        for (int nf = 0; nf < 4; nf++)
#pragma unroll
            for (int e = 0; e < 4; e++) acc[mf][nf][e] = 0.f;

#pragma unroll
    for (int q = 0; q < 4; q++) {
        float* d = As + (am + q * 32) * APITCH + ak4;
        d[0] = tf32_rna(pa[q].x); d[1] = tf32_rna(pa[q].y);
        d[2] = tf32_rna(pa[q].z); d[3] = tf32_rna(pa[q].w);
        float* e = Bs + (bk + q * 8) * BPITCH + bn4;
        e[0] = tf32_rna(pb[q].x); e[1] = tf32_rna(pb[q].y);
        e[2] = tf32_rna(pb[q].z); e[3] = tf32_rna(pb[q].w);
    }
    __syncthreads();

    for (int ch = 0; ch < NCH; ch++) {
        if (ch + 1 < NCH) {
            const int k0 = (ch + 1) * 32;
#pragma unroll
            for (int q = 0; q < 4; q++) {
                pa[q] = *(const float4*)(Aptr + (size_t)(q * 32) * KD + k0);
                pb[q] = *(const float4*)(Wptr + (size_t)(k0 + q * 8) * NW);
            }
        }

        const float* Sa = As + (ch & 1) * 128 * APITCH;
        const float* Sb = Bs + (ch & 1) * 32 * BPITCH;
#pragma unroll
        for (int ks = 0; ks < 4; ks++) {
            const int kk = ks * 8;
            uint32_t a[4][4], b[4][2];
#pragma unroll
            for (int mf = 0; mf < 4; mf++) {
                const float* pav = Sa + (warpM * 64 + mf * 16 + t4) * APITCH + kk + tm4;
                a[mf][0] = __float_as_uint(pav[0]);
                a[mf][1] = __float_as_uint(pav[8 * APITCH]);
                a[mf][2] = __float_as_uint(pav[4]);
                a[mf][3] = __float_as_uint(pav[8 * APITCH + 4]);
            }
#pragma unroll
            for (int nf = 0; nf < 4; nf++) {
                const float* pbv = Sb + (kk + tm4) * BPITCH + warpN * 32 + nf * 8 + t4;
                b[nf][0] = __float_as_uint(pbv[0]);
                b[nf][1] = __float_as_uint(pbv[4 * BPITCH]);
            }
#pragma unroll
            for (int mf = 0; mf < 4; mf++)
#pragma unroll
                for (int nf = 0; nf < 4; nf++)
                    MMA_TF32(acc[mf][nf][0], acc[mf][nf][1], acc[mf][nf][2], acc[mf][nf][3],
                             a[mf][0], a[mf][1], a[mf][2], a[mf][3],
                             b[nf][0], b[nf][1]);
        }

        if (ch + 1 < NCH) {
            float* Da = As + ((ch + 1) & 1) * 128 * APITCH;
            float* Db = Bs + ((ch + 1) & 1) * 32 * BPITCH;
#pragma unroll
            for (int q = 0; q < 4; q++) {
                float* d = Da + (am + q * 32) * APITCH + ak4;
                d[0] = tf32_rna(pa[q].x); d[1] = tf32_rna(pa[q].y);
                d[2] = tf32_rna(pa[q].z); d[3] = tf32_rna(pa[q].w);
                float* e = Db + (bk + q * 8) * BPITCH + bn4;
                e[0] = tf32_rna(pb[q].x); e[1] = tf32_rna(pb[q].y);
                e[2] = tf32_rna(pb[q].z); e[3] = tf32_rna(pb[q].w);
            }
        }
        __syncthreads();
    }

#pragma unroll
    for (int mf = 0; mf < 4; mf++) {
#pragma unroll
        for (int nf = 0; nf < 4; nf++) {
            const int col = bn + warpN * 32 + nf * 8 + 2 * tm4;
            const float2 bv = *(const float2*)(bias + col);
#pragma unroll
            for (int half = 0; half < 2; half++) {
                const int m = bm + warpM * 64 + mf * 16 + t4 + half * 8;
                float ox = acc[mf][nf][half * 2 + 0] + bv.x;
                float oy = acc[mf][nf][half * 2 + 1] + bv.y;
                if (MODE == 0) {
                    float2 o = make_float2(ox, oy);
                    *(float2*)(Cout + (size_t)m * NHD_ + col) = o;
                } else {
                    const int b = m >> 11;
                    const int s = m & (S_ - 1);
                    const int which = col >> 10;
                    const int rem   = col & 1023;
                    const int n = rem >> 6;
                    const int h = rem & 63;
                    ox = tf32_rna(ox); oy = tf32_rna(oy);
                    if (which == 1) {   // K -> [B,N,H,S]
                        float* dst = g_k + (((size_t)b * NH_ + n) * HD_ + h) * S_ + s;
                        dst[0]  = ox;
                        dst[S_] = oy;
                    } else {            // Q,V -> [B,N,S,H]
                        float* dst = (which == 0) ? g_q : g_v;
                        float2 o = make_float2(ox, oy);
                        *(float2*)(dst + (((size_t)b * NH_ + n) * S_ + s) * HD_ + h) = o;
                    }
                }
            }
        }
    }
}

// ---------------------------------------------------------------------------
// TF32 mma.sync causal flash attention.
// 128 threads (4 warps); CTA = 64 queries; key tiles of 64.
// Warp w owns query rows [16w,16w+16). Q frags in registers.
// smem: Ks[64][72] (d,key) | Vs[64][72] (key,h) | Ps[64][68] (q,key / Q stage)
#define KPIT 72
#define PPIT 68

__global__ __launch_bounds__(128)
void flash_mma()
{
    extern __shared__ float sm[];
    float* Ks = sm;
    float* Vs = Ks + 64 * KPIT;
    float* Ps = Vs + 64 * KPIT;

    const int tid  = threadIdx.x;
    const int wid  = tid >> 5;
    const int lane = tid & 31;
    const int t4   = lane >> 2;
    const int tm4  = lane & 3;
    const int qt   = gridDim.x - 1 - blockIdx.x;   // big tiles first
    const int bn   = blockIdx.y;
    const int b    = bn >> 4;
    const int n    = bn & 15;

    const float* Qg = g_q + ((size_t)bn * S_ + (size_t)qt * 64) * HD_;
    const float* Kg = g_k + (size_t)bn * HD_ * S_;   // [H][S]
    const float* Vg = g_v + (size_t)bn * S_ * HD_;   // [S][H]

    // stage Q tile -> Ps ([q][d], pitch PPIT)
    {
        const int q  = tid >> 4;
        const int dg = (tid & 15) * 4;
#pragma unroll
        for (int i = 0; i < 8; i++) {
            float4 v = *(const float4*)(Qg + (size_t)(q + i * 8) * HD_ + dg);
            *(float4*)(Ps + (q + i * 8) * PPIT + dg) = v;
        }
    }
    __syncthreads();

    // Q fragments (warp-local 16 rows)
    float qf[8][4];
#pragma unroll
    for (int kf = 0; kf < 8; kf++) {
        const float* p = Ps + (wid * 16 + t4) * PPIT + kf * 8 + tm4;
        qf[kf][0] = p[0];
        qf[kf][1] = p[8 * PPIT];
        qf[kf][2] = p[4];
        qf[kf][3] = p[8 * PPIT + 4];
    }
    __syncthreads();   // all warps done reading staged Q before Ps is reused

    float of[8][4];
#pragma unroll
    for (int nf = 0; nf < 8; nf++)
#pragma unroll
        for (int e = 0; e < 4; e++) of[nf][e] = 0.f;
    float m0 = -1e30f, m1 = -1e30f, l0 = 0.f, l1 = 0.f;

    const int nK = qt + 1;
    for (int kt = 0; kt < nK; kt++) {
        // load K (d,key) and V (key,h)
        {
            const int r  = tid >> 4;
            const int cg = (tid & 15) * 4;
#pragma unroll
            for (int i = 0; i < 8; i++) {
                const int rr = r + i * 8;
                *(float4*)(Ks + rr * KPIT + cg) =
                    *(const float4*)(Kg + (size_t)rr * S_ + kt * 64 + cg);
                *(float4*)(Vs + rr * KPIT + cg) =
                    *(const float4*)(Vg + (size_t)(kt * 64 + rr) * HD_ + cg);
            }
        }
        __syncthreads();

        // S = Q K^T
        float sf[8][4];
#pragma unroll
        for (int nf = 0; nf < 8; nf++)
#pragma unroll
            for (int e = 0; e < 4; e++) sf[nf][e] = 0.f;
#pragma unroll
        for (int kf = 0; kf < 8; kf++) {
            const uint32_t a0 = __float_as_uint(qf[kf][0]);
            const uint32_t a1 = __float_as_uint(qf[kf][1]);
            const uint32_t a2 = __float_as_uint(qf[kf][2]);
            const uint32_t a3 = __float_as_uint(qf[kf][3]);
#pragma unroll
            for (int nf = 0; nf < 8; nf++) {
                const float* pb = Ks + (kf * 8 + tm4) * KPIT + nf * 8 + t4;
                MMA_TF32(sf[nf][0], sf[nf][1], sf[nf][2], sf[nf][3],
                         a0, a1, a2, a3,
                         __float_as_uint(pb[0]), __float_as_uint(pb[4 * KPIT]));
            }
        }

        // scale + causal mask + online softmax
        const bool diag = (kt == qt);
        float mn0 = m0, mn1 = m1;
#pragma unroll
        for (int nf = 0; nf < 8; nf++) {
#pragma unroll
            for (int e = 0; e < 4; e++) {
                float v = sf[nf][e] * 0.125f;
                if (diag) {
                    const int kcol = nf * 8 + 2 * tm4 + (e & 1);
                    const int qrow = wid * 16 + t4 + ((e >= 2) ? 8 : 0);
                    if (kcol > qrow) v = -1e30f;
                }
                sf[nf][e] = v;
            }
            mn0 = fmaxf(mn0, fmaxf(sf[nf][0], sf[nf][1]));
            mn1 = fmaxf(mn1, fmaxf(sf[nf][2], sf[nf][3]));
        }
        mn0 = fmaxf(mn0, __shfl_xor_sync(0xffffffffu, mn0, 1));
        mn0 = fmaxf(mn0, __shfl_xor_sync(0xffffffffu, mn0, 2));
        mn1 = fmaxf(mn1, __shfl_xor_sync(0xffffffffu, mn1, 1));
        mn1 = fmaxf(mn1, __shfl_xor_sync(0xffffffffu, mn1, 2));
        const float corr0 = __expf(m0 - mn0);
        const float corr1 = __expf(m1 - mn1);
        m0 = mn0; m1 = mn1;

        float rs0 = 0.f, rs1 = 0.f;
#pragma unroll
        for (int nf = 0; nf < 8; nf++) {
            sf[nf][0] = __expf(sf[nf][0] - mn0);
            sf[nf][1] = __expf(sf[nf][1] - mn0);
            sf[nf][2] = __expf(sf[nf][2] - mn1);
            sf[nf][3] = __expf(sf[nf][3] - mn1);
            rs0 += sf[nf][0] + sf[nf][1];
            rs1 += sf[nf][2] + sf[nf][3];
            float* pp = Ps + (wid * 16 + t4) * PPIT + nf * 8 + 2 * tm4;
            pp[0]            = tf32_rna(sf[nf][0]);
            pp[1]            = tf32_rna(sf[nf][1]);
            pp[8 * PPIT]     = tf32_rna(sf[nf][2]);
            pp[8 * PPIT + 1] = tf32_rna(sf[nf][3]);
        }
        rs0 += __shfl_xor_sync(0xffffffffu, rs0, 1);
        rs0 += __shfl_xor_sync(0xffffffffu, rs0, 2);
        rs1 += __shfl_xor_sync(0xffffffffu, rs1, 1);
        rs1 += __shfl_xor_sync(0xffffffffu, rs1, 2);
        l0 = l0 * corr0 + rs0;
        l1 = l1 * corr1 + rs1;
#pragma unroll
        for (int nf = 0; nf < 8; nf++) {
            of[nf][0] *= corr0; of[nf][1] *= corr0;
            of[nf][2] *= corr1; of[nf][3] *= corr1;
        }
        __syncwarp();

        // O += P V
#pragma unroll
        for (int kf = 0; kf < 8; kf++) {
            const float* pa = Ps + (wid * 16 + t4) * PPIT + kf * 8 + tm4;
            const uint32_t a0 = __float_as_uint(pa[0]);
            const uint32_t a1 = __float_as_uint(pa[8 * PPIT]);
            const uint32_t a2 = __float_as_uint(pa[4]);
            const uint32_t a3 = __float_as_uint(pa[8 * PPIT + 4]);
#pragma unroll
            for (int nf = 0; nf < 8; nf++) {
                const float* pv = Vs + (kf * 8 + tm4) * KPIT + nf * 8 + t4;
                MMA_TF32(of[nf][0], of[nf][1], of[nf][2], of[nf][3],
                         a0, a1, a2, a3,
                         __float_as_uint(pv[0]), __float_as_uint(pv[4 * KPIT]));
            }
        }
        __syncthreads();
    }

    // epilogue -> g_ao [B,S,N*H]
    const float inv0 = 1.f / l0;
    const float inv1 = 1.f / l1;
    const int row0 = qt * 64 + wid * 16 + t4;
    float* dst0 = g_ao + ((size_t)b * S_ + row0) * NHD_ + n * 64;
    float* dst1 = dst0 + (size_t)8 * NHD_;
#pragma unroll
    for (int nf = 0; nf < 8; nf++) {
        const int c = nf * 8 + 2 * tm4;
        *(float2*)(dst0 + c) = make_float2(of[nf][0] * inv0, of[nf][1] * inv0);
        *(float2*)(dst1 + c) = make_float2(of[nf][2] * inv1, of[nf][3] * inv1);
    }
}

// ---------------------------------------------------------------------------
extern "C" void kernel_launch(void* const* d_in, const int* in_sizes, int n_in,
                              void* d_out, int out_size)
{
    const float* x    = (const float*)d_in[0];
    const float* Wqkv = (const float*)d_in[1];
    const float* bqkv = (const float*)d_in[2];
    const float* Wout = (const float*)d_in[3];
    const float* bout = (const float*)d_in[4];
    float* out = (float*)d_out;

    const int gemm_smem  = (2 * 128 * APITCH + 2 * 32 * BPITCH) * sizeof(float); // 70656
    const int flash_smem = (2 * 64 * KPIT + 64 * PPIT) * sizeof(float);           // 54272
    cudaFuncSetAttribute(mma_gemm<1>, cudaFuncAttributeMaxDynamicSharedMemorySize, gemm_smem);
    cudaFuncSetAttribute(mma_gemm<0>, cudaFuncAttributeMaxDynamicSharedMemorySize, gemm_smem);
    cudaFuncSetAttribute(flash_mma, cudaFuncAttributeMaxDynamicSharedMemorySize, flash_smem);

    // 1) QKV projection + bias; Q,V -> [B,N,S,H], K -> [B,N,H,S]; tf32-rounded
    mma_gemm<1><<<dim3(QKV_ / 128, M_ / 128), 256, gemm_smem>>>(x, Wqkv, bqkv, nullptr);
    // 2) causal flash attention (tensor cores) -> g_ao
    flash_mma<<<dim3(S_ / 64, B_ * NH_), 128, flash_smem>>>();
    // 3) output projection + bias -> d_out
    mma_gemm<0><<<dim3(NHD_ / 128, M_ / 128), 256, gemm_smem>>>(nullptr, Wout, bout, out);
}

// round 8
// speedup vs baseline: 5.6917x; 1.6535x over previous
#include <cuda_runtime.h>
#include <cuda_fp16.h>
#include <cstdint>
#include <math.h>

#define B_   4
#define S_   2048
#define E_   1024
#define NH_  16
#define HD_  64
#define M_   (B_ * S_)        // 8192
#define QKV_ (3 * NH_ * HD_)  // 3072
#define NHD_ (NH_ * HD_)      // 1024
#define KD   1024
#define NCH  (KD / 32)        // 32 chunks of 32 k (16 kpairs)
#define AP2  20               // A smem pitch (u32/half2 units)
#define BP2  136              // B smem pitch (u32 units)
#define KP2  72               // flash K/V smem pitch
#define PP2  36               // flash P/Q smem pitch

// ---- scratch: 64 MiB total (inside proven-safe 128 MiB envelope) -----------
__device__ __half g_q[B_ * NH_ * S_ * HD_];   // [B,N,S,H]
__device__ __half g_k[B_ * NH_ * S_ * HD_];   // [B,N,H,S] (d-major)
__device__ __half g_v[B_ * NH_ * S_ * HD_];   // [B,N,S,H]
__device__ __half g_ao[B_ * S_ * NHD_];       // [B,S,N*H]

// ---------------- helpers ---------------------------------------------------
// pack2(lo,hi): half2 with lo in low 16 bits (k-even in lo, per mma fragment)
__device__ __forceinline__ uint32_t pack2(float lo, float hi) {
    uint32_t r;
    asm("cvt.rn.f16x2.f32 %0, %1, %2;" : "=r"(r) : "f"(hi), "f"(lo));
    return r;
}
#define MMA_F16(c0, c1, c2, c3, a0, a1, a2, a3, b0, b1)                       \
    asm volatile(                                                             \
        "mma.sync.aligned.m16n8k16.row.col.f32.f16.f16.f32 "                  \
        "{%0,%1,%2,%3}, {%4,%5,%6,%7}, {%8,%9}, {%0,%1,%2,%3};"               \
        : "+f"(c0), "+f"(c1), "+f"(c2), "+f"(c3)                              \
        : "r"(a0), "r"(a1), "r"(a2), "r"(a3), "r"(b0), "r"(b1))

// ---------------------------------------------------------------------------
// FP16 mma.sync GEMM: C[128x128 tile] = A[M,1024] @ W[1024,Nn] + bias
// MODE 1: A = x (fp32, cvt on load), W=W_qkv -> halves into g_q/g_k/g_v
// MODE 0: A = g_ao (fp16 already),  W=W_out -> fp32 Cout
// 8 warps (2m x 4n), warp tile 64x32, m16n8k16 frags.
// smem(u32): As[2][128][20] + Bs[2][16][136] = 9472 u32 = 37888 B
template <int MODE>
__global__ __launch_bounds__(256)
void mma_gemm(const float* __restrict__ Ain, const float* __restrict__ W,
              const float* __restrict__ bias, float* __restrict__ Cout)
{
    const int NW = (MODE == 1) ? QKV_ : NHD_;
    extern __shared__ uint32_t smu[];
    uint32_t* As = smu;                    // 2 x 128 x AP2
    uint32_t* Bs = smu + 2 * 128 * AP2;    // 2 x 16 x BP2

    const int tid  = threadIdx.x;
    const int wid  = tid >> 5;
    const int lane = tid & 31;
    const int warpM = wid & 1;
    const int warpN = wid >> 1;
    const int t4  = lane >> 2;
    const int tm4 = lane & 3;

    const int bn = blockIdx.x * 128, bm = blockIdx.y * 128;

    // loader geometry
    const int ar  = tid >> 3;            // A row 0..31 (+32/q)
    const int ak4 = (tid & 7) * 4;       // A k offset (4 floats / 2 kpairs)
    const int bkp = tid >> 5;            // B kpair 0..7 (+8/q)
    const int bn4 = (tid & 31) * 4;      // B n offset
    const float*  Aptr_f = Ain + (size_t)(bm + ar) * KD + ak4;
    const __half* Aptr_h = g_ao + (size_t)(bm + ar) * KD + ak4;
    const float*  Wp0 = W + (size_t)(2 * bkp) * NW + bn + bn4;

    float4 pa_f[4]; uint2 pa_h[4]; float4 pwa[2], pwb[2];

    // ---- prologue global fetch (chunk 0)
#pragma unroll
    for (int q = 0; q < 4; q++) {
        if (MODE == 1) pa_f[q] = *(const float4*)(Aptr_f + (size_t)(q * 32) * KD);
        else           pa_h[q] = *(const uint2*)(Aptr_h + (size_t)(q * 32) * KD);
    }
#pragma unroll
    for (int q = 0; q < 2; q++) {
        const float* wp = Wp0 + (size_t)(q * 16) * NW;
        pwa[q] = *(const float4*)wp;
        pwb[q] = *(const float4*)(wp + NW);
    }

    float acc[4][4][4];
#pragma unroll
    for (int mf = 0; mf < 4; mf++)
#pragma unroll
        for (int nf = 0; nf < 4; nf++)
#pragma unroll
            for (int e = 0; e < 4; e++) acc[mf][nf][e] = 0.f;

    // ---- store prologue to stage 0
#pragma unroll
    for (int q = 0; q < 4; q++) {
        uint32_t* d = As + (ar + q * 32) * AP2 + (ak4 >> 1);
        if (MODE == 1) { d[0] = pack2(pa_f[q].x, pa_f[q].y); d[1] = pack2(pa_f[q].z, pa_f[q].w); }
        else           { d[0] = pa_h[q].x; d[1] = pa_h[q].y; }
    }
#pragma unroll
    for (int q = 0; q < 2; q++) {
        uint4 v;
        v.x = pack2(pwa[q].x, pwb[q].x); v.y = pack2(pwa[q].y, pwb[q].y);
        v.z = pack2(pwa[q].z, pwb[q].z); v.w = pack2(pwa[q].w, pwb[q].w);
        *(uint4*)(Bs + (bkp + q * 8) * BP2 + bn4) = v;
    }
    __syncthreads();

    for (int ch = 0; ch < NCH; ch++) {
        if (ch + 1 < NCH) {
            const int k0 = (ch + 1) * 32;
#pragma unroll
            for (int q = 0; q < 4; q++) {
                if (MODE == 1) pa_f[q] = *(const float4*)(Aptr_f + (size_t)(q * 32) * KD + k0);
                else           pa_h[q] = *(const uint2*)(Aptr_h + (size_t)(q * 32) * KD + k0);
            }
#pragma unroll
            for (int q = 0; q < 2; q++) {
                const float* wp = Wp0 + (size_t)(k0 + q * 16) * NW;
                pwa[q] = *(const float4*)wp;
                pwb[q] = *(const float4*)(wp + NW);
            }
        }

        const uint32_t* Sa = As + (ch & 1) * 128 * AP2;
        const uint32_t* Sb = Bs + (ch & 1) * 16 * BP2;
#pragma unroll
        for (int s = 0; s < 2; s++) {           // two k16 steps per 32-chunk
            const int kk = s * 8;
            uint32_t a[4][4], b[4][2];
#pragma unroll
            for (int mf = 0; mf < 4; mf++) {
                const uint32_t* pav = Sa + (warpM * 64 + mf * 16 + t4) * AP2 + kk + tm4;
                a[mf][0] = pav[0];
                a[mf][1] = pav[8 * AP2];
                a[mf][2] = pav[4];
                a[mf][3] = pav[8 * AP2 + 4];
            }
#pragma unroll
            for (int nf = 0; nf < 4; nf++) {
                const uint32_t* pbv = Sb + (kk + tm4) * BP2 + warpN * 32 + nf * 8 + t4;
                b[nf][0] = pbv[0];
                b[nf][1] = pbv[4 * BP2];
            }
#pragma unroll
            for (int mf = 0; mf < 4; mf++)
#pragma unroll
                for (int nf = 0; nf < 4; nf++)
                    MMA_F16(acc[mf][nf][0], acc[mf][nf][1], acc[mf][nf][2], acc[mf][nf][3],
                            a[mf][0], a[mf][1], a[mf][2], a[mf][3],
                            b[nf][0], b[nf][1]);
        }

        if (ch + 1 < NCH) {
            uint32_t* Da = As + ((ch + 1) & 1) * 128 * AP2;
            uint32_t* Db = Bs + ((ch + 1) & 1) * 16 * BP2;
#pragma unroll
            for (int q = 0; q < 4; q++) {
                uint32_t* d = Da + (ar + q * 32) * AP2 + (ak4 >> 1);
                if (MODE == 1) { d[0] = pack2(pa_f[q].x, pa_f[q].y); d[1] = pack2(pa_f[q].z, pa_f[q].w); }
                else           { d[0] = pa_h[q].x; d[1] = pa_h[q].y; }
            }
#pragma unroll
            for (int q = 0; q < 2; q++) {
                uint4 v;
                v.x = pack2(pwa[q].x, pwb[q].x); v.y = pack2(pwa[q].y, pwb[q].y);
                v.z = pack2(pwa[q].z, pwb[q].z); v.w = pack2(pwa[q].w, pwb[q].w);
                *(uint4*)(Db + (bkp + q * 8) * BP2 + bn4) = v;
            }
        }
        __syncthreads();
    }

    // ---- epilogue
#pragma unroll
    for (int mf = 0; mf < 4; mf++) {
#pragma unroll
        for (int nf = 0; nf < 4; nf++) {
            const int col = bn + warpN * 32 + nf * 8 + 2 * tm4;
            const float2 bv = *(const float2*)(bias + col);
#pragma unroll
            for (int half_ = 0; half_ < 2; half_++) {
                const int m = bm + warpM * 64 + mf * 16 + t4 + half_ * 8;
                const float ox = acc[mf][nf][half_ * 2 + 0] + bv.x;
                const float oy = acc[mf][nf][half_ * 2 + 1] + bv.y;
                if (MODE == 0) {
                    *(float2*)(Cout + (size_t)m * NHD_ + col) = make_float2(ox, oy);
                } else {
                    const int b = m >> 11;
                    const int s = m & (S_ - 1);
                    const int which = col >> 10;
                    const int rem   = col & 1023;
                    const int n = rem >> 6;
                    const int h = rem & 63;
                    if (which == 1) {   // K -> [B,N,H,S] (d-major), halves
                        __half* dst = g_k + (((size_t)b * NH_ + n) * HD_ + h) * S_ + s;
                        dst[0]  = __float2half_rn(ox);
                        dst[S_] = __float2half_rn(oy);
                    } else {            // Q,V -> [B,N,S,H], half2 (h even)
                        __half* dst = (which == 0) ? g_q : g_v;
                        *(uint32_t*)(dst + (((size_t)b * NH_ + n) * S_ + s) * HD_ + h) =
                            pack2(ox, oy);
                    }
                }
            }
        }
    }
}

// ---------------------------------------------------------------------------
// FP16 mma.sync causal flash attention. 128 threads / 4 warps; 64q x 64k tiles.
// smem(u32): Ks[32][72] (dpair,key) | Vs[32][72] (kpair,h) | Ps[64][36] (q,kpair)
__global__ __launch_bounds__(128)
void flash_mma()
{
    extern __shared__ uint32_t smu[];
    uint32_t* Ks = smu;
    uint32_t* Vs = smu + 32 * KP2;
    uint32_t* Ps = smu + 2 * 32 * KP2;

    const int tid  = threadIdx.x;
    const int wid  = tid >> 5;
    const int lane = tid & 31;
    const int t4   = lane >> 2;
    const int tm4  = lane & 3;
    const int qt   = gridDim.x - 1 - blockIdx.x;   // big causal tiles first
    const int bn   = blockIdx.y;
    const int b    = bn >> 4;
    const int n    = bn & 15;

    const __half* Qg = g_q + ((size_t)bn * S_ + (size_t)qt * 64) * HD_;
    const __half* Kg = g_k + (size_t)bn * HD_ * S_;   // [H][S]
    const __half* Vg = g_v + (size_t)bn * S_ * HD_;   // [S][H]

    // stage Q tile (warp-private rows) -> Ps [row][dpair]
    {
        const int row = tid >> 1;
        const int c0  = (tid & 1) * 16;
        const uint32_t* src = (const uint32_t*)(Qg + (size_t)row * HD_) + c0;
        uint32_t* dst = Ps + row * PP2 + c0;
#pragma unroll
        for (int i = 0; i < 4; i++) ((uint4*)dst)[i] = ((const uint4*)src)[i];
    }
    __syncwarp();

    uint32_t qf[4][4];
#pragma unroll
    for (int s = 0; s < 4; s++) {
        const uint32_t* p = Ps + (wid * 16 + t4) * PP2 + s * 8 + tm4;
        qf[s][0] = p[0];
        qf[s][1] = p[8 * PP2];
        qf[s][2] = p[4];
        qf[s][3] = p[8 * PP2 + 4];
    }
    __syncwarp();

    float of[8][4];
#pragma unroll
    for (int nf = 0; nf < 8; nf++)
#pragma unroll
        for (int e = 0; e < 4; e++) of[nf][e] = 0.f;
    float m0 = -1e30f, m1 = -1e30f, l0 = 0.f, l1 = 0.f;

    const int nK = qt + 1;
    for (int kt = 0; kt < nK; kt++) {
        // load K (pack d-pairs) and V (pack key-pairs)
        {
            const int r2  = tid >> 2;        // dp (K) / kp (V), 0..31
            const int c16 = (tid & 3) * 16;  // key/h offset
            const __half* kr = Kg + (size_t)(2 * r2) * S_ + (size_t)kt * 64 + c16;
            const __half* vr = Vg + ((size_t)kt * 64 + 2 * r2) * HD_ + c16;
#pragma unroll
            for (int i = 0; i < 2; i++) {
                uint4 ka = ((const uint4*)kr)[i];
                uint4 kb = ((const uint4*)(kr + S_))[i];
                uint32_t* kd = Ks + r2 * KP2 + c16 + i * 8;
                kd[0] = __byte_perm(ka.x, kb.x, 0x5410); kd[1] = __byte_perm(ka.x, kb.x, 0x7632);
                kd[2] = __byte_perm(ka.y, kb.y, 0x5410); kd[3] = __byte_perm(ka.y, kb.y, 0x7632);
                kd[4] = __byte_perm(ka.z, kb.z, 0x5410); kd[5] = __byte_perm(ka.z, kb.z, 0x7632);
                kd[6] = __byte_perm(ka.w, kb.w, 0x5410); kd[7] = __byte_perm(ka.w, kb.w, 0x7632);
                uint4 va = ((const uint4*)vr)[i];
                uint4 vb = ((const uint4*)(vr + HD_))[i];
                uint32_t* vd = Vs + r2 * KP2 + c16 + i * 8;
                vd[0] = __byte_perm(va.x, vb.x, 0x5410); vd[1] = __byte_perm(va.x, vb.x, 0x7632);
                vd[2] = __byte_perm(va.y, vb.y, 0x5410); vd[3] = __byte_perm(va.y, vb.y, 0x7632);
                vd[4] = __byte_perm(va.z, vb.z, 0x5410); vd[5] = __byte_perm(va.z, vb.z, 0x7632);
                vd[6] = __byte_perm(va.w, vb.w, 0x5410); vd[7] = __byte_perm(va.w, vb.w, 0x7632);
            }
        }
        __syncthreads();

        // S = Q K^T
        float sf[8][4];
#pragma unroll
        for (int nf = 0; nf < 8; nf++)
#pragma unroll
            for (int e = 0; e < 4; e++) sf[nf][e] = 0.f;
#pragma unroll
        for (int s = 0; s < 4; s++) {
#pragma unroll
            for (int nf = 0; nf < 8; nf++) {
                const uint32_t* pb = Ks + (s * 8 + tm4) * KP2 + nf * 8 + t4;
                MMA_F16(sf[nf][0], sf[nf][1], sf[nf][2], sf[nf][3],
                        qf[s][0], qf[s][1], qf[s][2], qf[s][3],
                        pb[0], pb[4 * KP2]);
            }
        }

        // scale + causal mask + online softmax
        const bool diag = (kt == qt);
        float mn0 = m0, mn1 = m1;
#pragma unroll
        for (int nf = 0; nf < 8; nf++) {
#pragma unroll
            for (int e = 0; e < 4; e++) {
                float v = sf[nf][e] * 0.125f;
                if (diag) {
                    const int kcol = nf * 8 + 2 * tm4 + (e & 1);
                    const int qrow = wid * 16 + t4 + ((e >= 2) ? 8 : 0);
                    if (kcol > qrow) v = -1e30f;
                }
                sf[nf][e] = v;
            }
            mn0 = fmaxf(mn0, fmaxf(sf[nf][0], sf[nf][1]));
            mn1 = fmaxf(mn1, fmaxf(sf[nf][2], sf[nf][3]));
        }
        mn0 = fmaxf(mn0, __shfl_xor_sync(0xffffffffu, mn0, 1));
        mn0 = fmaxf(mn0, __shfl_xor_sync(0xffffffffu, mn0, 2));
        mn1 = fmaxf(mn1, __shfl_xor_sync(0xffffffffu, mn1, 1));
        mn1 = fmaxf(mn1, __shfl_xor_sync(0xffffffffu, mn1, 2));
        const float corr0 = __expf(m0 - mn0);
        const float corr1 = __expf(m1 - mn1);
        m0 = mn0; m1 = mn1;

        float rs0 = 0.f, rs1 = 0.f;
#pragma unroll
        for (int nf = 0; nf < 8; nf++) {
            const float e0 = __expf(sf[nf][0] - mn0);
            const float e1 = __expf(sf[nf][1] - mn0);
            const float e2 = __expf(sf[nf][2] - mn1);
            const float e3 = __expf(sf[nf][3] - mn1);
            rs0 += e0 + e1;
            rs1 += e2 + e3;
            uint32_t* pp = Ps + (wid * 16 + t4) * PP2 + nf * 4 + tm4;
            pp[0]        = pack2(e0, e1);
            pp[8 * PP2]  = pack2(e2, e3);
        }
        rs0 += __shfl_xor_sync(0xffffffffu, rs0, 1);
        rs0 += __shfl_xor_sync(0xffffffffu, rs0, 2);
        rs1 += __shfl_xor_sync(0xffffffffu, rs1, 1);
        rs1 += __shfl_xor_sync(0xffffffffu, rs1, 2);
        l0 = l0 * corr0 + rs0;
        l1 = l1 * corr1 + rs1;
#pragma unroll
        for (int nf = 0; nf < 8; nf++) {
            of[nf][0] *= corr0; of[nf][1] *= corr0;
            of[nf][2] *= corr1; of[nf][3] *= corr1;
        }
        __syncwarp();

        // O += P V
#pragma unroll
        for (int s = 0; s < 4; s++) {
            const uint32_t* pa = Ps + (wid * 16 + t4) * PP2 + s * 8 + tm4;
            const uint32_t a0 = pa[0];
            const uint32_t a1 = pa[8 * PP2];
            const uint32_t a2 = pa[4];
            const uint32_t a3 = pa[8 * PP2 + 4];
#pragma unroll
            for (int nf = 0; nf < 8; nf++) {
                const uint32_t* pv = Vs + (s * 8 + tm4) * KP2 + nf * 8 + t4;
                MMA_F16(of[nf][0], of[nf][1], of[nf][2], of[nf][3],
                        a0, a1, a2, a3, pv[0], pv[4 * KP2]);
            }
        }
        __syncthreads();
    }

    // epilogue -> g_ao [B,S,N*H] fp16
    const float inv0 = 1.f / l0;
    const float inv1 = 1.f / l1;
    const int row0 = qt * 64 + wid * 16 + t4;
    __half* d0 = g_ao + ((size_t)b * S_ + row0) * NHD_ + n * 64;
    __half* d1 = d0 + (size_t)8 * NHD_;
#pragma unroll
    for (int nf = 0; nf < 8; nf++) {
        const int c = nf * 8 + 2 * tm4;
        *(uint32_t*)(d0 + c) = pack2(of[nf][0] * inv0, of[nf][1] * inv0);
        *(uint32_t*)(d1 + c) = pack2(of[nf][2] * inv1, of[nf][3] * inv1);
    }
}

// ---------------------------------------------------------------------------
extern "C" void kernel_launch(void* const* d_in, const int* in_sizes, int n_in,
                              void* d_out, int out_size)
{
    const float* x    = (const float*)d_in[0];
    const float* Wqkv = (const float*)d_in[1];
    const float* bqkv = (const float*)d_in[2];
    const float* Wout = (const float*)d_in[3];
    const float* bout = (const float*)d_in[4];
    float* out = (float*)d_out;

    const int gemm_smem  = (2 * 128 * AP2 + 2 * 16 * BP2) * 4;       // 37888
    const int flash_smem = (2 * 32 * KP2 + 64 * PP2) * 4;            // 27648
    cudaFuncSetAttribute(mma_gemm<1>, cudaFuncAttributeMaxDynamicSharedMemorySize, gemm_smem);
    cudaFuncSetAttribute(mma_gemm<0>, cudaFuncAttributeMaxDynamicSharedMemorySize, gemm_smem);
    cudaFuncSetAttribute(flash_mma, cudaFuncAttributeMaxDynamicSharedMemorySize, flash_smem);

    // 1) QKV projection (fp16 mma) -> half q/k/v; K stored d-major
    mma_gemm<1><<<dim3(QKV_ / 128, M_ / 128), 256, gemm_smem>>>(x, Wqkv, bqkv, nullptr);
    // 2) causal flash attention (fp16 mma) -> g_ao
    flash_mma<<<dim3(S_ / 64, B_ * NH_), 128, flash_smem>>>();
    // 3) output projection (fp16 mma) -> fp32 d_out
    mma_gemm<0><<<dim3(NHD_ / 128, M_ / 128), 256, gemm_smem>>>(nullptr, Wout, bout, out);
}

// round 11
// speedup vs baseline: 6.5418x; 1.1494x over previous
#include <cuda_runtime.h>
#include <cuda_fp16.h>
#include <cstdint>
#include <math.h>

#define B_   4
#define S_   2048
#define E_   1024
#define NH_  16
#define HD_  64
#define M_   (B_ * S_)        // 8192
#define QKV_ (3 * NH_ * HD_)  // 3072
#define NHD_ (NH_ * HD_)      // 1024
#define KD   1024
#define NCH  (KD / 32)        // 32 chunks of 32 k (16 kpairs)
#define AP2  20               // A smem pitch (u32 units)
#define BP2  136              // B smem pitch (u32 units)
#define KP2  72               // flash K/V smem pitch
#define PP2  36               // flash P/Q smem pitch

// ---- scratch ----------------------------------------------------------------
// RULE (discovered R3-R10): __device__ globals must ONLY be referenced from
// device code. Passing one as a kernel argument from host code passes the
// host shadow address -> ATS paging -> 128 MiB driver arena -> guard trip.
__device__ __half   g_q[B_ * NH_ * S_ * HD_];   // [B,N,S,H]
__device__ __half   g_k[B_ * NH_ * S_ * HD_];   // [B,N,H,S] (d-major)
__device__ __half   g_v[B_ * NH_ * S_ * HD_];   // [B,N,S,H]
__device__ __half   g_ao[B_ * S_ * NHD_];       // [B,S,N*H]
__device__ __half   g_xh[M_ * E_];              // x in fp16
__device__ uint32_t g_wqp[(KD / 2) * QKV_];     // W_qkv packed half2-kpair
__device__ uint32_t g_wop[(KD / 2) * NHD_];     // W_out packed

// ---------------- helpers ---------------------------------------------------
// pack2(lo,hi): half2 with lo in low 16 bits (k-even in lo, per mma fragment)
__device__ __forceinline__ uint32_t pack2(float lo, float hi) {
    uint32_t r;
    asm("cvt.rn.f16x2.f32 %0, %1, %2;" : "=r"(r) : "f"(hi), "f"(lo));
    return r;
}
#define MMA_F16(c0, c1, c2, c3, a0, a1, a2, a3, b0, b1)                       \
    asm volatile(                                                             \
        "mma.sync.aligned.m16n8k16.row.col.f32.f16.f16.f32 "                  \
        "{%0,%1,%2,%3}, {%4,%5,%6,%7}, {%8,%9}, {%0,%1,%2,%3};"               \
        : "+f"(c0), "+f"(c1), "+f"(c2), "+f"(c3)                              \
        : "r"(a0), "r"(a1), "r"(a2), "r"(a3), "r"(b0), "r"(b1))

// ---------------------------------------------------------------------------
// prep: x (fp32, harness ptr) -> g_xh (fp16). 8 floats per thread.
__global__ __launch_bounds__(256)
void cvt_x_kernel(const float* __restrict__ x)
{
    const size_t i = ((size_t)blockIdx.x * 256 + threadIdx.x) * 8;
    const float4 v0 = *(const float4*)(x + i);
    const float4 v1 = *(const float4*)(x + i + 4);
    uint4 o;
    o.x = pack2(v0.x, v0.y); o.y = pack2(v0.z, v0.w);
    o.z = pack2(v1.x, v1.y); o.w = pack2(v1.z, v1.w);
    *(uint4*)(g_xh + i) = o;
}
// prep: W [K][NW] fp32 -> g_wqp/g_wop [K/2][NW] u32 (destination bound in device code)
template <int MODE>   // 1 -> g_wqp (NW=QKV_), 0 -> g_wop (NW=NHD_)
__global__ __launch_bounds__(256)
void pack_w_kernel(const float* __restrict__ W)
{
    const int NW = (MODE == 1) ? QKV_ : NHD_;
    uint32_t* Wp = (MODE == 1) ? g_wqp : g_wop;
    const int i  = blockIdx.x * 256 + threadIdx.x;
    const int kp = i / (NW / 4);
    const int c4 = (i % (NW / 4)) * 4;
    const float* w0 = W + (size_t)(2 * kp) * NW + c4;
    const float4 a = *(const float4*)w0;
    const float4 b = *(const float4*)(w0 + NW);
    uint4 o;
    o.x = pack2(a.x, b.x); o.y = pack2(a.y, b.y);
    o.z = pack2(a.z, b.z); o.w = pack2(a.w, b.w);
    *(uint4*)(Wp + (size_t)kp * NW + c4) = o;
}

// ---------------------------------------------------------------------------
// FP16 mma.sync GEMM: C[128x128 tile] = A[M,1024] @ W[1024,Nn] + bias
// A fp16 (g_xh or g_ao), W pre-packed (g_wqp or g_wop) -- all device-bound.
// Inner loop: pure uint4 smem traffic + MMA (no cvt).
template <int MODE>
__global__ __launch_bounds__(256)
void mma_gemm(const float* __restrict__ bias, float* __restrict__ Cout)
{
    const int NW = (MODE == 1) ? QKV_ : NHD_;
    const uint32_t* __restrict__ Wp = (MODE == 1) ? g_wqp : g_wop;
    extern __shared__ uint32_t smu[];
    uint32_t* As = smu;                    // 2 x 128 x AP2
    uint32_t* Bs = smu + 2 * 128 * AP2;    // 2 x 16 x BP2

    const int tid  = threadIdx.x;
    const int wid  = tid >> 5;
    const int lane = tid & 31;
    const int warpM = wid & 1;
    const int warpN = wid >> 1;
    const int t4  = lane >> 2;
    const int tm4 = lane & 3;

    const int bn = blockIdx.x * 128, bm = blockIdx.y * 128;
    const __half* Ag = (MODE == 1) ? g_xh : g_ao;

    // loader geometry: per stage 2048 u32 per operand, 2 x uint4 per thread
    const int ar   = (tid >> 2);           // A row 0..63 (+64 on q=1)
    const int aseg = (tid & 3) * 4;        // A u32 seg {0,4,8,12}
    const int brow = (tid >> 5);           // B kpair 0..7 (+8 on q=1)
    const int bc4  = (tid & 31) * 4;       // B col {0..124}
    const __half*   Ap0 = Ag + (size_t)(bm + ar) * KD + aseg * 2;
    const __half*   Ap1 = Ag + (size_t)(bm + ar + 64) * KD + aseg * 2;
    const uint32_t* Wp0 = Wp + (size_t)brow * NW + bn + bc4;
    const uint32_t* Wp1 = Wp + (size_t)(brow + 8) * NW + bn + bc4;

    uint4 pa0, pa1, pb0, pb1;
    pa0 = *(const uint4*)Ap0;
    pa1 = *(const uint4*)Ap1;
    pb0 = *(const uint4*)Wp0;
    pb1 = *(const uint4*)Wp1;

    float acc[4][4][4];
#pragma unroll
    for (int mf = 0; mf < 4; mf++)
#pragma unroll
        for (int nf = 0; nf < 4; nf++)
#pragma unroll
            for (int e = 0; e < 4; e++) acc[mf][nf][e] = 0.f;

    *(uint4*)(As + ar * AP2 + aseg) = pa0;
    *(uint4*)(As + (ar + 64) * AP2 + aseg) = pa1;
    *(uint4*)(Bs + brow * BP2 + bc4) = pb0;
    *(uint4*)(Bs + (brow + 8) * BP2 + bc4) = pb1;
    __syncthreads();

    for (int ch = 0; ch < NCH; ch++) {
        if (ch + 1 < NCH) {
            const int kh = (ch + 1) * 32;        // halfs
            const int kr = (ch + 1) * 16;        // kpair rows
            pa0 = *(const uint4*)(Ap0 + kh);
            pa1 = *(const uint4*)(Ap1 + kh);
            pb0 = *(const uint4*)(Wp0 + (size_t)kr * NW);
            pb1 = *(const uint4*)(Wp1 + (size_t)kr * NW);
        }

        const uint32_t* Sa = As + (ch & 1) * 128 * AP2;
        const uint32_t* Sb = Bs + (ch & 1) * 16 * BP2;
#pragma unroll
        for (int s = 0; s < 2; s++) {
            const int kk = s * 8;
            uint32_t a[4][4], b[4][2];
#pragma unroll
            for (int mf = 0; mf < 4; mf++) {
                const uint32_t* pav = Sa + (warpM * 64 + mf * 16 + t4) * AP2 + kk + tm4;
                a[mf][0] = pav[0];
                a[mf][1] = pav[8 * AP2];
                a[mf][2] = pav[4];
                a[mf][3] = pav[8 * AP2 + 4];
            }
#pragma unroll
            for (int nf = 0; nf < 4; nf++) {
                const uint32_t* pbv = Sb + (kk + tm4) * BP2 + warpN * 32 + nf * 8 + t4;
                b[nf][0] = pbv[0];
                b[nf][1] = pbv[4 * BP2];
            }
#pragma unroll
            for (int mf = 0; mf < 4; mf++)
#pragma unroll
                for (int nf = 0; nf < 4; nf++)
                    MMA_F16(acc[mf][nf][0], acc[mf][nf][1], acc[mf][nf][2], acc[mf][nf][3],
                            a[mf][0], a[mf][1], a[mf][2], a[mf][3],
                            b[nf][0], b[nf][1]);
        }

        if (ch + 1 < NCH) {
            uint32_t* Da = As + ((ch + 1) & 1) * 128 * AP2;
            uint32_t* Db = Bs + ((ch + 1) & 1) * 16 * BP2;
            *(uint4*)(Da + ar * AP2 + aseg) = pa0;
            *(uint4*)(Da + (ar + 64) * AP2 + aseg) = pa1;
            *(uint4*)(Db + brow * BP2 + bc4) = pb0;
            *(uint4*)(Db + (brow + 8) * BP2 + bc4) = pb1;
        }
        __syncthreads();
    }

    // ---- epilogue
#pragma unroll
    for (int mf = 0; mf < 4; mf++) {
#pragma unroll
        for (int nf = 0; nf < 4; nf++) {
            const int col = bn + warpN * 32 + nf * 8 + 2 * tm4;
            const float2 bv = *(const float2*)(bias + col);
#pragma unroll
            for (int half_ = 0; half_ < 2; half_++) {
                const int m = bm + warpM * 64 + mf * 16 + t4 + half_ * 8;
                const float ox = acc[mf][nf][half_ * 2 + 0] + bv.x;
                const float oy = acc[mf][nf][half_ * 2 + 1] + bv.y;
                if (MODE == 0) {
                    *(float2*)(Cout + (size_t)m * NHD_ + col) = make_float2(ox, oy);
                } else {
                    const int b = m >> 11;
                    const int s = m & (S_ - 1);
                    const int which = col >> 10;
                    const int rem   = col & 1023;
                    const int n = rem >> 6;
                    const int h = rem & 63;
                    if (which == 1) {   // K -> [B,N,H,S] (d-major), halves
                        __half* dst = g_k + (((size_t)b * NH_ + n) * HD_ + h) * S_ + s;
                        dst[0]  = __float2half_rn(ox);
                        dst[S_] = __float2half_rn(oy);
                    } else {            // Q,V -> [B,N,S,H], half2 (h even)
                        __half* dst = (which == 0) ? g_q : g_v;
                        *(uint32_t*)(dst + (((size_t)b * NH_ + n) * S_ + s) * HD_ + h) =
                            pack2(ox, oy);
                    }
                }
            }
        }
    }
}

// ---------------------------------------------------------------------------
// FP16 mma.sync causal flash attention (unchanged from R8, which passed).
__global__ __launch_bounds__(128)
void flash_mma()
{
    extern __shared__ uint32_t smu[];
    uint32_t* Ks = smu;
    uint32_t* Vs = smu + 32 * KP2;
    uint32_t* Ps = smu + 2 * 32 * KP2;

    const int tid  = threadIdx.x;
    const int wid  = tid >> 5;
    const int lane = tid & 31;
    const int t4   = lane >> 2;
    const int tm4  = lane & 3;
    const int qt   = gridDim.x - 1 - blockIdx.x;
    const int bn   = blockIdx.y;
    const int b    = bn >> 4;
    const int n    = bn & 15;

    const __half* Qg = g_q + ((size_t)bn * S_ + (size_t)qt * 64) * HD_;
    const __half* Kg = g_k + (size_t)bn * HD_ * S_;
    const __half* Vg = g_v + (size_t)bn * S_ * HD_;

    {
        const int row = tid >> 1;
        const int c0  = (tid & 1) * 16;
        const uint32_t* src = (const uint32_t*)(Qg + (size_t)row * HD_) + c0;
        uint32_t* dst = Ps + row * PP2 + c0;
#pragma unroll
        for (int i = 0; i < 4; i++) ((uint4*)dst)[i] = ((const uint4*)src)[i];
    }
    __syncwarp();

    uint32_t qf[4][4];
#pragma unroll
    for (int s = 0; s < 4; s++) {
        const uint32_t* p = Ps + (wid * 16 + t4) * PP2 + s * 8 + tm4;
        qf[s][0] = p[0];
        qf[s][1] = p[8 * PP2];
        qf[s][2] = p[4];
        qf[s][3] = p[8 * PP2 + 4];
    }
    __syncwarp();

    float of[8][4];
#pragma unroll
    for (int nf = 0; nf < 8; nf++)
#pragma unroll
        for (int e = 0; e < 4; e++) of[nf][e] = 0.f;
    float m0 = -1e30f, m1 = -1e30f, l0 = 0.f, l1 = 0.f;

    const int nK = qt + 1;
    for (int kt = 0; kt < nK; kt++) {
        {
            const int r2  = tid >> 2;
            const int c16 = (tid & 3) * 16;
            const __half* kr = Kg + (size_t)(2 * r2) * S_ + (size_t)kt * 64 + c16;
            const __half* vr = Vg + ((size_t)kt * 64 + 2 * r2) * HD_ + c16;
#pragma unroll
            for (int i = 0; i < 2; i++) {
                uint4 ka = ((const uint4*)kr)[i];
                uint4 kb = ((const uint4*)(kr + S_))[i];
                uint32_t* kd = Ks + r2 * KP2 + c16 + i * 8;
                kd[0] = __byte_perm(ka.x, kb.x, 0x5410); kd[1] = __byte_perm(ka.x, kb.x, 0x7632);
                kd[2] = __byte_perm(ka.y, kb.y, 0x5410); kd[3] = __byte_perm(ka.y, kb.y, 0x7632);
                kd[4] = __byte_perm(ka.z, kb.z, 0x5410); kd[5] = __byte_perm(ka.z, kb.z, 0x7632);
                kd[6] = __byte_perm(ka.w, kb.w, 0x5410); kd[7] = __byte_perm(ka.w, kb.w, 0x7632);
                uint4 va = ((const uint4*)vr)[i];
                uint4 vb = ((const uint4*)(vr + HD_))[i];
                uint32_t* vd = Vs + r2 * KP2 + c16 + i * 8;
                vd[0] = __byte_perm(va.x, vb.x, 0x5410); vd[1] = __byte_perm(va.x, vb.x, 0x7632);
                vd[2] = __byte_perm(va.y, vb.y, 0x5410); vd[3] = __byte_perm(va.y, vb.y, 0x7632);
                vd[4] = __byte_perm(va.z, vb.z, 0x5410); vd[5] = __byte_perm(va.z, vb.z, 0x7632);
                vd[6] = __byte_perm(va.w, vb.w, 0x5410); vd[7] = __byte_perm(va.w, vb.w, 0x7632);
            }
        }
        __syncthreads();

        float sf[8][4];
#pragma unroll
        for (int nf = 0; nf < 8; nf++)
#pragma unroll
            for (int e = 0; e < 4; e++) sf[nf][e] = 0.f;
#pragma unroll
        for (int s = 0; s < 4; s++) {
#pragma unroll
            for (int nf = 0; nf < 8; nf++) {
                const uint32_t* pb = Ks + (s * 8 + tm4) * KP2 + nf * 8 + t4;
                MMA_F16(sf[nf][0], sf[nf][1], sf[nf][2], sf[nf][3],
                        qf[s][0], qf[s][1], qf[s][2], qf[s][3],
                        pb[0], pb[4 * KP2]);
            }
        }

        const bool diag = (kt == qt);
        float mn0 = m0, mn1 = m1;
#pragma unroll
        for (int nf = 0; nf < 8; nf++) {
#pragma unroll
            for (int e = 0; e < 4; e++) {
                float v = sf[nf][e] * 0.125f;
                if (diag) {
                    const int kcol = nf * 8 + 2 * tm4 + (e & 1);
                    const int qrow = wid * 16 + t4 + ((e >= 2) ? 8 : 0);
                    if (kcol > qrow) v = -1e30f;
                }
                sf[nf][e] = v;
            }
            mn0 = fmaxf(mn0, fmaxf(sf[nf][0], sf[nf][1]));
            mn1 = fmaxf(mn1, fmaxf(sf[nf][2], sf[nf][3]));
        }
        mn0 = fmaxf(mn0, __shfl_xor_sync(0xffffffffu, mn0, 1));
        mn0 = fmaxf(mn0, __shfl_xor_sync(0xffffffffu, mn0, 2));
        mn1 = fmaxf(mn1, __shfl_xor_sync(0xffffffffu, mn1, 1));
        mn1 = fmaxf(mn1, __shfl_xor_sync(0xffffffffu, mn1, 2));
        const float corr0 = __expf(m0 - mn0);
        const float corr1 = __expf(m1 - mn1);
        m0 = mn0; m1 = mn1;

        float rs0 = 0.f, rs1 = 0.f;
#pragma unroll
        for (int nf = 0; nf < 8; nf++) {
            const float e0 = __expf(sf[nf][0] - mn0);
            const float e1 = __expf(sf[nf][1] - mn0);
            const float e2 = __expf(sf[nf][2] - mn1);
            const float e3 = __expf(sf[nf][3] - mn1);
            rs0 += e0 + e1;
            rs1 += e2 + e3;
            uint32_t* pp = Ps + (wid * 16 + t4) * PP2 + nf * 4 + tm4;
            pp[0]        = pack2(e0, e1);
            pp[8 * PP2]  = pack2(e2, e3);
        }
        rs0 += __shfl_xor_sync(0xffffffffu, rs0, 1);
        rs0 += __shfl_xor_sync(0xffffffffu, rs0, 2);
        rs1 += __shfl_xor_sync(0xffffffffu, rs1, 1);
        rs1 += __shfl_xor_sync(0xffffffffu, rs1, 2);
        l0 = l0 * corr0 + rs0;
        l1 = l1 * corr1 + rs1;
#pragma unroll
        for (int nf = 0; nf < 8; nf++) {
            of[nf][0] *= corr0; of[nf][1] *= corr0;
            of[nf][2] *= corr1; of[nf][3] *= corr1;
        }
        __syncwarp();

#pragma unroll
        for (int s = 0; s < 4; s++) {
            const uint32_t* pa = Ps + (wid * 16 + t4) * PP2 + s * 8 + tm4;
            const uint32_t a0 = pa[0];
            const uint32_t a1 = pa[8 * PP2];
            const uint32_t a2 = pa[4];
            const uint32_t a3 = pa[8 * PP2 + 4];
#pragma unroll
            for (int nf = 0; nf < 8; nf++) {
                const uint32_t* pv = Vs + (s * 8 + tm4) * KP2 + nf * 8 + t4;
                MMA_F16(of[nf][0], of[nf][1], of[nf][2], of[nf][3],
                        a0, a1, a2, a3, pv[0], pv[4 * KP2]);
            }
        }
        __syncthreads();
    }

    const float inv0 = 1.f / l0;
    const float inv1 = 1.f / l1;
    const int row0 = qt * 64 + wid * 16 + t4;
    __half* d0 = g_ao + ((size_t)b * S_ + row0) * NHD_ + n * 64;
    __half* d1 = d0 + (size_t)8 * NHD_;
#pragma unroll
    for (int nf = 0; nf < 8; nf++) {
        const int c = nf * 8 + 2 * tm4;
        *(uint32_t*)(d0 + c) = pack2(of[nf][0] * inv0, of[nf][1] * inv0);
        *(uint32_t*)(d1 + c) = pack2(of[nf][2] * inv1, of[nf][3] * inv1);
    }
}

// ---------------------------------------------------------------------------
extern "C" void kernel_launch(void* const* d_in, const int* in_sizes, int n_in,
                              void* d_out, int out_size)
{
    // ONLY harness pointers cross the host/device boundary.
    const float* x    = (const float*)d_in[0];
    const float* Wqkv = (const float*)d_in[1];
    const float* bqkv = (const float*)d_in[2];
    const float* Wout = (const float*)d_in[3];
    const float* bout = (const float*)d_in[4];
    float* out = (float*)d_out;

    const int gemm_smem  = (2 * 128 * AP2 + 2 * 16 * BP2) * 4;       // 37888
    const int flash_smem = (2 * 32 * KP2 + 64 * PP2) * 4;            // 27648
    cudaFuncSetAttribute(mma_gemm<1>, cudaFuncAttributeMaxDynamicSharedMemorySize, gemm_smem);
    cudaFuncSetAttribute(mma_gemm<0>, cudaFuncAttributeMaxDynamicSharedMemorySize, gemm_smem);
    cudaFuncSetAttribute(flash_mma, cudaFuncAttributeMaxDynamicSharedMemorySize, flash_smem);

    // prep: fp16 conversion / weight packing (destinations bound device-side)
    cvt_x_kernel<<<(M_ * E_) / (256 * 8), 256>>>(x);
    pack_w_kernel<1><<<(KD / 2) * QKV_ / 4 / 256, 256>>>(Wqkv);
    pack_w_kernel<0><<<(KD / 2) * NHD_ / 4 / 256, 256>>>(Wout);

    // 1) QKV projection -> half q/k/v; K stored d-major
    mma_gemm<1><<<dim3(QKV_ / 128, M_ / 128), 256, gemm_smem>>>(bqkv, nullptr);
    // 2) causal flash attention -> g_ao
    flash_mma<<<dim3(S_ / 64, B_ * NH_), 128, flash_smem>>>();
    // 3) output projection -> fp32 d_out
    mma_gemm<0><<<dim3(NHD_ / 128, M_ / 128), 256, gemm_smem>>>(bout, out);
}